// round 14
// baseline (speedup 1.0000x reference)
#include <cuda_runtime.h>
#include <stdint.h>

#define NPIX 65536
#define NIMG 4
#define EMAX 131072            // >= 2*256*255 grid edges per image
#define CAP  16384             // minima cap (expected ~13.1k for this data)
#define NTHR 1024

// dynamic smem layout (phase overlays), total 229376 B <= 227KB limit
#define SEL_OFF    32768       // Boruvka: par u16[CAP] @0, sel u64[CAP] @32768 (ends 163840)
#define BIRTH_OFF  32768       // pairing: par u16[CAP] @0, birth u32[CAP] @32768
#define LIFE_OFF   98304       // pairing: life f32[CAP] @98304 (ends 163840)
#define CAND_OFF   163840      // top-5 candidates: 1024*5 f32 (ends 184320)
#define SMEM_BYTES 229376

// ---------------- device scratch (no allocations allowed) -------------------
__device__ uint32_t           g_fbits[NIMG * NPIX];
__device__ unsigned long long g_edges[NIMG * EMAX];
__device__ unsigned long long g_edgesB[NIMG * EMAX];
__device__ unsigned long long g_mstA[NIMG * CAP];
__device__ unsigned long long g_mstB[NIMG * CAP];
__device__ uint32_t           g_birth[NIMG * CAP];
__device__ float              g_loss[NIMG];
__device__ int                g_done;              // static-zero; reset by last block

__device__ __forceinline__ uint32_t uf_find(uint16_t* par, uint32_t x) {
    uint32_t p = par[x];
    while (p != x) {                     // path halving
        uint32_t g = par[p];
        par[x] = (uint16_t)g;
        x = g;
        p = par[x];
    }
    return x;
}

__device__ __forceinline__ void top5_ins(float& t0, float& t1, float& t2,
                                         float& t3, float& t4, float life) {
    if (life <= t4) return;
    if (life > t0)      { t4 = t3; t3 = t2; t2 = t1; t1 = t0; t0 = life; }
    else if (life > t1) { t4 = t3; t3 = t2; t2 = t1; t1 = life; }
    else if (life > t2) { t4 = t3; t3 = t2; t2 = life; }
    else if (life > t3) { t4 = t3; t3 = life; }
    else                  t4 = life;
}

// =============================================================================
// One block per image: the entire PH-0 pipeline with shared-memory overlays.
// =============================================================================
__global__ void __launch_bounds__(NTHR, 1)
k_fused(const float* __restrict__ prob, const float* __restrict__ roi,
        float* __restrict__ out) {
    extern __shared__ char sm[];
    __shared__ uint32_t warpsum[32];
    __shared__ int s_flag, s_hook, s_ecnt, s_mcnt, s_nmin, s_cnt2;

    const int img  = blockIdx.x;
    const int tid  = threadIdx.x;
    const int lane = tid & 31;
    const int wid  = tid >> 5;
    const unsigned FULL = 0xFFFFFFFFu;

    uint32_t* fb = g_fbits + (size_t)img * NPIX;
    uint16_t* B  = (uint16_t*)sm;                 // pixel->parent / basin / dense id

    if (tid == 0) { s_ecnt = 0; s_mcnt = 0; }

    // ---- P0: f = 1 - prob*roi, store float bits (f>0 -> bit order == order)
    for (int i = tid; i < NPIX; i += NTHR) {
        int gi = img * NPIX + i;
        fb[i] = __float_as_uint(1.0f - prob[gi] * roi[gi]);
    }
    __syncthreads();

    // ---- P1: steepest-descent parent by key (fbits, pix)
    for (int i = tid; i < NPIX; i += NTHR) {
        unsigned long long k0 = ((unsigned long long)fb[i] << 16) | (unsigned)i;
        int y = i >> 8, x = i & 255;
        unsigned long long kb = ~0ull;
        if (y > 0)   { unsigned long long k = ((unsigned long long)fb[i-256] << 16) | (unsigned)(i-256); if (k < kb) kb = k; }
        if (y < 255) { unsigned long long k = ((unsigned long long)fb[i+256] << 16) | (unsigned)(i+256); if (k < kb) kb = k; }
        if (x > 0)   { unsigned long long k = ((unsigned long long)fb[i-1]   << 16) | (unsigned)(i-1);   if (k < kb) kb = k; }
        if (x < 255) { unsigned long long k = ((unsigned long long)fb[i+1]   << 16) | (unsigned)(i+1);   if (k < kb) kb = k; }
        B[i] = (kb < k0) ? (uint16_t)(kb & 0xFFFFu) : (uint16_t)i;
    }
    __syncthreads();

    // ---- P2: pointer doubling to basin roots, early exit (uniform barriers)
    for (;;) {
        if (tid == 0) s_flag = 0;
        __syncthreads();
        for (int i = tid; i < NPIX; i += NTHR) {
            uint32_t p = B[i];
            uint32_t g = B[p];
            if (g != p) { B[i] = (uint16_t)g; s_flag = 1; }
        }
        __syncthreads();
        int f = s_flag;
        __syncthreads();
        if (!f) break;
    }

    // ---- P3: dense minima ids (pixel order) + birth fbits; rewrite B -> dense
    const int chbase = tid * 64;
    unsigned long long rootmask = 0ull;
    uint32_t cnt = 0;
    for (int j = 0; j < 64; j++) {
        if (B[chbase + j] == (uint16_t)(chbase + j)) { rootmask |= 1ull << j; cnt++; }
    }
    {   // block exclusive scan of cnt (thread-chunk order; uniform trip count)
        uint32_t v = cnt;
        #pragma unroll
        for (int o = 1; o < 32; o <<= 1) {
            uint32_t n = __shfl_up_sync(FULL, v, o);
            if (lane >= o) v += n;
        }
        if (lane == 31) warpsum[wid] = v;
        __syncthreads();
        if (wid == 0) {
            uint32_t w = warpsum[lane], wv = w;
            #pragma unroll
            for (int o = 1; o < 32; o <<= 1) {
                uint32_t n = __shfl_up_sync(FULL, wv, o);
                if (lane >= o) wv += n;
            }
            warpsum[lane] = wv - w;
        }
        __syncthreads();
        uint32_t run = (v - cnt) + warpsum[wid];
        if (tid == NTHR - 1) s_nmin = (int)(run + cnt);
        // step b: roots get dense id; record birth fbits
        uint32_t r = run;
        for (int j = 0; j < 64; j++) {
            if ((rootmask >> j) & 1ull) {
                int i = chbase + j;
                g_birth[(size_t)img * CAP + r] = fb[i];
                B[i] = (uint16_t)r;
                r++;
            }
        }
    }
    __syncthreads();
    // step c: non-roots: B[i] = dense(B_old[i]) (root entries already dense)
    for (int j = 0; j < 64; j++) {
        if (!((rootmask >> j) & 1ull)) {
            int i = chbase + j;
            B[i] = B[B[i]];
        }
    }
    __syncthreads();
    const int nmin = s_nmin;

    // ---- P4: crossing edges (right/down), record (death_fbits | cu | cv)
    // NPIX is a multiple of NTHR -> warp shuffles always fully converged.
    unsigned long long* ed  = g_edges  + (size_t)img * EMAX;
    unsigned long long* edB = g_edgesB + (size_t)img * EMAX;
    for (int i = tid; i < NPIX; i += NTHR) {
        uint32_t f0 = fb[i];
        uint32_t cu = B[i];
        int y = i >> 8, x = i & 255;
        unsigned long long recs[2];
        int c = 0;
        if (x < 255) {
            uint32_t cv = B[i + 1];
            if (cv != cu) {
                uint32_t f1 = fb[i + 1];
                uint32_t d = f0 > f1 ? f0 : f1;
                recs[c++] = ((unsigned long long)d << 32) | ((unsigned long long)cu << 16) | cv;
            }
        }
        if (y < 255) {
            uint32_t cv = B[i + 256];
            if (cv != cu) {
                uint32_t f1 = fb[i + 256];
                uint32_t d = f0 > f1 ? f0 : f1;
                recs[c++] = ((unsigned long long)d << 32) | ((unsigned long long)cu << 16) | cv;
            }
        }
        int pre = c;
        #pragma unroll
        for (int o = 1; o < 32; o <<= 1) {
            int n = __shfl_up_sync(FULL, pre, o);
            if (lane >= o) pre += n;
        }
        int total = __shfl_sync(FULL, pre, 31);
        int excl = pre - c;
        int bs = 0;
        if (lane == 31 && total > 0) bs = atomicAdd(&s_ecnt, total);
        bs = __shfl_sync(FULL, bs, 31);
        for (int j = 0; j < c; j++) ed[bs + excl + j] = recs[j];
    }
    __syncthreads();

    // ---- P5: Boruvka MST, per-round edge compaction (ping-pong gmem)
    {
        uint16_t* par = (uint16_t*)sm;
        unsigned long long* sel = (unsigned long long*)(sm + SEL_OFF);
        unsigned long long* mst = g_mstA + (size_t)img * CAP;
        unsigned long long* src = ed;
        unsigned long long* dst = edB;
        int mcur = s_ecnt;
        for (int i = tid; i < nmin; i += NTHR) par[i] = (uint16_t)i;

        for (int round = 0; round < 24; round++) {
            if (tid == 0) { s_hook = 0; s_cnt2 = 0; }
            for (int i = tid; i < nmin; i += NTHR) sel[i] = ~0ull;
            __syncthreads();

            // lightest external edge per component: key=(fb<<16)|other
            for (int e = tid; e < mcur; e += NTHR) {
                unsigned long long E = src[e];
                uint32_t lo = (uint32_t)E;
                uint32_t cu = lo >> 16, cv = lo & 0xFFFFu;
                unsigned long long fbw = E >> 32;
                atomicMin(&sel[cu], (fbw << 16) | cv);
                atomicMin(&sel[cv], (fbw << 16) | cu);
            }
            __syncthreads();

            // hook (mutual 2-cycles: smaller id stays root) + record MST edge
            for (int c = tid; c < nmin; c += NTHR) {
                unsigned long long s = sel[c];
                if (s == ~0ull) continue;
                uint32_t d = (uint32_t)(s & 0xFFFFu);
                unsigned long long sd = sel[d];
                bool mutual = ((uint32_t)(sd & 0xFFFFu) == (uint32_t)c);
                if (mutual && (uint32_t)c < d) continue;
                par[c] = (uint16_t)d;
                int pos = atomicAdd(&s_mcnt, 1);
                mst[pos] = ((s >> 16) << 32) | ((unsigned long long)c << 16) | d;
                s_hook = 1;
            }
            __syncthreads();
            int hooked = s_hook;
            __syncthreads();
            if (!hooked) break;

            // flatten with early exit (uniform barriers)
            for (;;) {
                if (tid == 0) s_flag = 0;
                __syncthreads();
                for (int i = tid; i < nmin; i += NTHR) {
                    uint32_t p = par[i];
                    uint32_t g = par[p];
                    if (g != p) { par[i] = (uint16_t)g; s_flag = 1; }
                }
                __syncthreads();
                int f = s_flag;
                __syncthreads();
                if (!f) break;
            }

            // relabel + compact surviving (still-crossing) edges into dst.
            // Uniform iteration count: all 32 lanes always reach the shuffles.
            const int iters = (mcur + NTHR - 1) >> 10;
            for (int k = 0; k < iters; k++) {
                int e = tid + (k << 10);
                unsigned long long rec = 0ull;
                int c = 0;
                if (e < mcur) {
                    unsigned long long E = src[e];
                    uint32_t lo = (uint32_t)E;
                    uint32_t cu = par[lo >> 16], cv = par[lo & 0xFFFFu];
                    if (cu != cv) {
                        rec = (E & 0xFFFFFFFF00000000ull)
                            | ((unsigned long long)cu << 16) | cv;
                        c = 1;
                    }
                }
                int pre = c;
                #pragma unroll
                for (int o = 1; o < 32; o <<= 1) {
                    int n = __shfl_up_sync(FULL, pre, o);
                    if (lane >= o) pre += n;
                }
                int total = __shfl_sync(FULL, pre, 31);
                int excl = pre - c;
                int bs = 0;
                if (lane == 31 && total > 0) bs = atomicAdd(&s_cnt2, total);
                bs = __shfl_sync(FULL, bs, 31);
                if (c) dst[bs + excl] = rec;
            }
            __syncthreads();
            mcur = s_cnt2;                         // uniform read; reset at top of
            { unsigned long long* t = src; src = dst; dst = t; }  // next round
            if (mcur == 0) break;
            __syncthreads();
        }
    }
    __syncthreads();
    const int m2 = s_mcnt;                        // == nmin - 1

    // ---- P6: 8x4-bit LSD radix sort of MST edges by death fbits (bits 32..63)
    {
        uint32_t* hist = (uint32_t*)sm;           // 64 KB (par/sel dead)
        const size_t off = (size_t)img * CAP;
        for (int pass = 0; pass < 8; pass++) {
            const unsigned long long* src = (pass & 1) ? g_mstB + off : g_mstA + off;
            unsigned long long*       dst = (pass & 1) ? g_mstA + off : g_mstB + off;
            const int shift = 32 + pass * 4;

            #pragma unroll
            for (int i = 0; i < 16; i++) hist[i * 1024 + tid] = 0;
            __syncthreads();

            const int bse = tid * 16;
            for (int j = 0; j < 16; j++) {
                int idx = bse + j;
                if (idx < m2) {
                    uint32_t d = (uint32_t)(src[idx] >> shift) & 15u;
                    hist[(d << 10) + tid]++;
                }
            }
            __syncthreads();

            const int sb = tid * 16;
            uint32_t sum = 0;
            #pragma unroll
            for (int i = 0; i < 16; i++) sum += hist[sb + i];
            uint32_t v = sum;
            #pragma unroll
            for (int o = 1; o < 32; o <<= 1) {
                uint32_t t = __shfl_up_sync(FULL, v, o);
                if (lane >= o) v += t;
            }
            if (lane == 31) warpsum[wid] = v;
            __syncthreads();
            if (wid == 0) {
                uint32_t w = warpsum[lane], wv = w;
                #pragma unroll
                for (int o = 1; o < 32; o <<= 1) {
                    uint32_t t = __shfl_up_sync(FULL, wv, o);
                    if (lane >= o) wv += t;
                }
                warpsum[lane] = wv - w;
            }
            __syncthreads();
            uint32_t run = (v - sum) + warpsum[wid];
            #pragma unroll
            for (int i = 0; i < 16; i++) { uint32_t t = hist[sb + i]; hist[sb + i] = run; run += t; }
            __syncthreads();

            for (int j = 0; j < 16; j++) {
                int idx = bse + j;
                if (idx < m2) {
                    unsigned long long k = src[idx];
                    uint32_t d = (uint32_t)(k >> shift) & 15u;
                    dst[hist[(d << 10) + tid]++] = k;
                }
            }
            __syncthreads();
        }
    }

    // ---- P7: warp-parallel Kruskal pairing with exact die-collision rule.
    // A root dies at most once; merges sharing only a SURVIVING root commute.
    // Per 32-edge chunk, rounds: (1) pending lanes find roots + compute
    // die/keep; (2) ordered 32-step shuffle scan finalizes commit flags in
    // lane order: lane j blocked iff an earlier active lane l shares a root
    // with j AND (l does not commit this round OR die_l hits j's roots);
    // (3) safe lanes commit in parallel. First pending lane always commits
    // -> guaranteed progress, no serial path.
    {
        uint16_t* par = (uint16_t*)sm;
        uint32_t* birth = (uint32_t*)(sm + BIRTH_OFF);
        float* life = (float*)(sm + LIFE_OFF);
        const unsigned long long* __restrict__ mste = g_mstA + (size_t)img * CAP;
        for (int i = tid; i < nmin; i += NTHR) {
            par[i] = (uint16_t)i;
            birth[i] = g_birth[(size_t)img * CAP + i];
        }
        __syncthreads();

        if (tid < 32) {
            for (int bs0 = 0; bs0 < m2; bs0 += 32) {   // uniform trip count
                int j = bs0 + lane;
                bool have = j < m2;
                unsigned long long e = have ? mste[j] : 0ull;
                uint32_t cu = (uint32_t)(e >> 16) & 0xFFFFu;
                uint32_t cv = (uint32_t)e & 0xFFFFu;
                float death = __uint_as_float((uint32_t)(e >> 32));
                bool done = !have;

                for (;;) {
                    unsigned pend = __ballot_sync(FULL, !done);
                    if (!pend) break;

                    uint32_t ru = 0, rv = 0, die = 0, keep = 0;
                    if (!done) {
                        ru = uf_find(par, cu);
                        rv = uf_find(par, cv);
                        uint32_t bu = birth[ru], bv = birth[rv];
                        bool ku = (bu < bv) || (bu == bv && ru < rv);  // elder survives
                        keep = ku ? ru : rv;
                        die  = ku ? rv : ru;
                    }
                    __syncwarp();

                    bool blocked = false;
                    uint32_t commitFlag = 0;
                    uint32_t act = (uint32_t)(!done);
                    #pragma unroll
                    for (int l = 0; l < 32; l++) {
                        if (lane == l) commitFlag = act & (uint32_t)(!blocked);
                        uint32_t rul  = __shfl_sync(FULL, ru, l);
                        uint32_t rvl  = __shfl_sync(FULL, rv, l);
                        uint32_t diel = __shfl_sync(FULL, die, l);
                        uint32_t actl = __shfl_sync(FULL, act, l);
                        uint32_t cml  = __shfl_sync(FULL, commitFlag, l);
                        if (lane > l && !done && actl) {
                            bool share  = (rul == ru) | (rul == rv) | (rvl == ru) | (rvl == rv);
                            bool lethal = (!cml) | (diel == ru) | (diel == rv);
                            if (share && lethal) blocked = true;
                        }
                    }

                    if (commitFlag) {
                        par[die] = (uint16_t)keep;
                        life[j] = death - __uint_as_float(birth[die]);
                        done = true;
                    }
                    __syncwarp();
                }
            }
        }
        __syncthreads();

        // ---- P8: block top-5 + per-image loss (dropped pairs all have life 0)
        float* cand = (float*)(sm + CAND_OFF);
        float t0 = -1e30f, t1 = -1e30f, t2 = -1e30f, t3 = -1e30f, t4 = -1e30f;
        for (int i = tid; i < m2; i += NTHR) top5_ins(t0, t1, t2, t3, t4, life[i]);
        cand[tid * 5 + 0] = t0; cand[tid * 5 + 1] = t1; cand[tid * 5 + 2] = t2;
        cand[tid * 5 + 3] = t3; cand[tid * 5 + 4] = t4;
        __syncthreads();
        if (tid == 0) {
            float s0 = -1e30f, s1 = -1e30f, s2 = -1e30f, s3 = -1e30f, s4 = -1e30f;
            for (int i = 0; i < NTHR * 5; i++) top5_ins(s0, s1, s2, s3, s4, cand[i]);
            if (s0 < -1e29f) s0 = 0.0f;        // pad with 0-life pairs (reference has 65535 pairs)
            if (s1 < -1e29f) s1 = 0.0f;
            if (s2 < -1e29f) s2 = 0.0f;
            if (s3 < -1e29f) s3 = 0.0f;
            if (s4 < -1e29f) s4 = 0.0f;
            float d0 = s0 - 0.5f, d1 = s1 - 0.5f, d2 = s2 - 0.5f, d3 = s3 - 0.5f, d4 = s4 - 0.5f;
            g_loss[img] = (d0 * d0 + d1 * d1 + d2 * d2 + d3 * d3 + d4 * d4) * 0.2f;

            // ---- fused final reduction: last block to arrive sums the losses
            __threadfence();
            int old = atomicAdd(&g_done, 1);
            if (old == NIMG - 1) {
                __threadfence();
                out[0] = (g_loss[0] + g_loss[1] + g_loss[2] + g_loss[3]) * 25.0f;
                g_done = 0;                    // reset for next graph replay
            }
        }
    }
}

// ---------------- launch -----------------------------------------------------
extern "C" void kernel_launch(void* const* d_in, const int* in_sizes, int n_in,
                              void* d_out, int out_size) {
    (void)in_sizes; (void)n_in; (void)out_size;
    const float* prob = (const float*)d_in[0];
    const float* roi  = (const float*)d_in[1];
    float* out = (float*)d_out;

    cudaFuncSetAttribute(k_fused, cudaFuncAttributeMaxDynamicSharedMemorySize, SMEM_BYTES);

    k_fused<<<NIMG, NTHR, SMEM_BYTES>>>(prob, roi, out);
}

// round 15
// speedup vs baseline: 1.5309x; 1.5309x over previous
#include <cuda_runtime.h>
#include <stdint.h>

#define NPIX 65536
#define NIMG 4
#define EMAX 131072            // >= 2*256*255 grid edges per image
#define CAP  16384             // minima cap (expected ~13.1k for this data)
#define NTHR 1024

// dynamic smem layout (phase overlays), total 229376 B <= 227KB limit
#define SEL_OFF    32768       // Boruvka: par u16[CAP] @0, sel u64[CAP] @32768 (ends 163840)
#define BIRTH_OFF  32768       // pairing: par u16[CAP] @0, birth u32[CAP] @32768
#define MSTE_OFF   98304       // pairing: mst u64[CAP] @98304 (ends 229376); life f32 overlays
#define SMEM_BYTES 229376

// ---------------- device scratch (no allocations allowed) -------------------
__device__ uint32_t           g_fbits[NIMG * NPIX];
__device__ unsigned long long g_edges[NIMG * EMAX];
__device__ unsigned long long g_edgesB[NIMG * EMAX];
__device__ unsigned long long g_mstA[NIMG * CAP];
__device__ unsigned long long g_mstB[NIMG * CAP];
__device__ uint32_t           g_birth[NIMG * CAP];
__device__ float              g_loss[NIMG];
__device__ int                g_done;              // static-zero; reset by last block

__device__ __forceinline__ uint32_t uf_find(uint16_t* par, uint32_t x) {
    uint32_t p = par[x];
    while (p != x) {                     // path halving
        uint32_t g = par[p];
        par[x] = (uint16_t)g;
        x = g;
        p = par[x];
    }
    return x;
}

__device__ __forceinline__ void top5_ins(float& t0, float& t1, float& t2,
                                         float& t3, float& t4, float life) {
    if (life <= t4) return;
    if (life > t0)      { t4 = t3; t3 = t2; t2 = t1; t1 = t0; t0 = life; }
    else if (life > t1) { t4 = t3; t3 = t2; t2 = t1; t1 = life; }
    else if (life > t2) { t4 = t3; t3 = t2; t2 = life; }
    else if (life > t3) { t4 = t3; t3 = life; }
    else                  t4 = life;
}

// =============================================================================
// One block per image: the entire PH-0 pipeline with shared-memory overlays.
// =============================================================================
__global__ void __launch_bounds__(NTHR, 1)
k_fused(const float* __restrict__ prob, const float* __restrict__ roi,
        float* __restrict__ out) {
    extern __shared__ char sm[];
    __shared__ uint32_t warpsum[32];
    __shared__ float cand2[32 * 5];
    __shared__ int s_flag, s_hook, s_ecnt, s_mcnt, s_nmin, s_cnt2;

    const int img  = blockIdx.x;
    const int tid  = threadIdx.x;
    const int lane = tid & 31;
    const int wid  = tid >> 5;
    const unsigned FULL = 0xFFFFFFFFu;

    uint32_t* fb = g_fbits + (size_t)img * NPIX;
    uint16_t* B  = (uint16_t*)sm;                 // pixel->parent / basin / dense id

    if (tid == 0) { s_ecnt = 0; s_mcnt = 0; }

    // ---- P0: f = 1 - prob*roi, store float bits (f>0 -> bit order == order)
    for (int i = tid; i < NPIX; i += NTHR) {
        int gi = img * NPIX + i;
        fb[i] = __float_as_uint(1.0f - prob[gi] * roi[gi]);
    }
    __syncthreads();

    // ---- P1: steepest-descent parent by key (fbits, pix)
    for (int i = tid; i < NPIX; i += NTHR) {
        unsigned long long k0 = ((unsigned long long)fb[i] << 16) | (unsigned)i;
        int y = i >> 8, x = i & 255;
        unsigned long long kb = ~0ull;
        if (y > 0)   { unsigned long long k = ((unsigned long long)fb[i-256] << 16) | (unsigned)(i-256); if (k < kb) kb = k; }
        if (y < 255) { unsigned long long k = ((unsigned long long)fb[i+256] << 16) | (unsigned)(i+256); if (k < kb) kb = k; }
        if (x > 0)   { unsigned long long k = ((unsigned long long)fb[i-1]   << 16) | (unsigned)(i-1);   if (k < kb) kb = k; }
        if (x < 255) { unsigned long long k = ((unsigned long long)fb[i+1]   << 16) | (unsigned)(i+1);   if (k < kb) kb = k; }
        B[i] = (kb < k0) ? (uint16_t)(kb & 0xFFFFu) : (uint16_t)i;
    }
    __syncthreads();

    // ---- P2: pointer doubling to basin roots, early exit (uniform barriers)
    for (;;) {
        if (tid == 0) s_flag = 0;
        __syncthreads();
        for (int i = tid; i < NPIX; i += NTHR) {
            uint32_t p = B[i];
            uint32_t g = B[p];
            if (g != p) { B[i] = (uint16_t)g; s_flag = 1; }
        }
        __syncthreads();
        int f = s_flag;
        __syncthreads();
        if (!f) break;
    }

    // ---- P3: dense minima ids (pixel order) + birth fbits; rewrite B -> dense
    const int chbase = tid * 64;
    unsigned long long rootmask = 0ull;
    uint32_t cnt = 0;
    for (int j = 0; j < 64; j++) {
        if (B[chbase + j] == (uint16_t)(chbase + j)) { rootmask |= 1ull << j; cnt++; }
    }
    {   // block exclusive scan of cnt (thread-chunk order; uniform trip count)
        uint32_t v = cnt;
        #pragma unroll
        for (int o = 1; o < 32; o <<= 1) {
            uint32_t n = __shfl_up_sync(FULL, v, o);
            if (lane >= o) v += n;
        }
        if (lane == 31) warpsum[wid] = v;
        __syncthreads();
        if (wid == 0) {
            uint32_t w = warpsum[lane], wv = w;
            #pragma unroll
            for (int o = 1; o < 32; o <<= 1) {
                uint32_t n = __shfl_up_sync(FULL, wv, o);
                if (lane >= o) wv += n;
            }
            warpsum[lane] = wv - w;
        }
        __syncthreads();
        uint32_t run = (v - cnt) + warpsum[wid];
        if (tid == NTHR - 1) s_nmin = (int)(run + cnt);
        // step b: roots get dense id; record birth fbits
        uint32_t r = run;
        for (int j = 0; j < 64; j++) {
            if ((rootmask >> j) & 1ull) {
                int i = chbase + j;
                g_birth[(size_t)img * CAP + r] = fb[i];
                B[i] = (uint16_t)r;
                r++;
            }
        }
    }
    __syncthreads();
    // step c: non-roots: B[i] = dense(B_old[i]) (root entries already dense)
    for (int j = 0; j < 64; j++) {
        if (!((rootmask >> j) & 1ull)) {
            int i = chbase + j;
            B[i] = B[B[i]];
        }
    }
    __syncthreads();
    const int nmin = s_nmin;

    // ---- P4: crossing edges (right/down), record (death_fbits | cu | cv)
    // NPIX is a multiple of NTHR -> warp shuffles always fully converged.
    unsigned long long* ed  = g_edges  + (size_t)img * EMAX;
    unsigned long long* edB = g_edgesB + (size_t)img * EMAX;
    for (int i = tid; i < NPIX; i += NTHR) {
        uint32_t f0 = fb[i];
        uint32_t cu = B[i];
        int y = i >> 8, x = i & 255;
        unsigned long long recs[2];
        int c = 0;
        if (x < 255) {
            uint32_t cv = B[i + 1];
            if (cv != cu) {
                uint32_t f1 = fb[i + 1];
                uint32_t d = f0 > f1 ? f0 : f1;
                recs[c++] = ((unsigned long long)d << 32) | ((unsigned long long)cu << 16) | cv;
            }
        }
        if (y < 255) {
            uint32_t cv = B[i + 256];
            if (cv != cu) {
                uint32_t f1 = fb[i + 256];
                uint32_t d = f0 > f1 ? f0 : f1;
                recs[c++] = ((unsigned long long)d << 32) | ((unsigned long long)cu << 16) | cv;
            }
        }
        int pre = c;
        #pragma unroll
        for (int o = 1; o < 32; o <<= 1) {
            int n = __shfl_up_sync(FULL, pre, o);
            if (lane >= o) pre += n;
        }
        int total = __shfl_sync(FULL, pre, 31);
        int excl = pre - c;
        int bs = 0;
        if (lane == 31 && total > 0) bs = atomicAdd(&s_ecnt, total);
        bs = __shfl_sync(FULL, bs, 31);
        for (int j = 0; j < c; j++) ed[bs + excl + j] = recs[j];
    }
    __syncthreads();

    // ---- P5: Boruvka MST, per-round edge compaction (ping-pong gmem)
    {
        uint16_t* par = (uint16_t*)sm;
        unsigned long long* sel = (unsigned long long*)(sm + SEL_OFF);
        unsigned long long* mst = g_mstA + (size_t)img * CAP;
        unsigned long long* src = ed;
        unsigned long long* dst = edB;
        int mcur = s_ecnt;
        for (int i = tid; i < nmin; i += NTHR) par[i] = (uint16_t)i;

        for (int round = 0; round < 24; round++) {
            if (tid == 0) { s_hook = 0; s_cnt2 = 0; }
            for (int i = tid; i < nmin; i += NTHR) sel[i] = ~0ull;
            __syncthreads();

            // lightest external edge per component: key=(fb<<16)|other
            for (int e = tid; e < mcur; e += NTHR) {
                unsigned long long E = src[e];
                uint32_t lo = (uint32_t)E;
                uint32_t cu = lo >> 16, cv = lo & 0xFFFFu;
                unsigned long long fbw = E >> 32;
                atomicMin(&sel[cu], (fbw << 16) | cv);
                atomicMin(&sel[cv], (fbw << 16) | cu);
            }
            __syncthreads();

            // hook (mutual 2-cycles: smaller id stays root) + record MST edge
            for (int c = tid; c < nmin; c += NTHR) {
                unsigned long long s = sel[c];
                if (s == ~0ull) continue;
                uint32_t d = (uint32_t)(s & 0xFFFFu);
                unsigned long long sd = sel[d];
                bool mutual = ((uint32_t)(sd & 0xFFFFu) == (uint32_t)c);
                if (mutual && (uint32_t)c < d) continue;
                par[c] = (uint16_t)d;
                int pos = atomicAdd(&s_mcnt, 1);
                mst[pos] = ((s >> 16) << 32) | ((unsigned long long)c << 16) | d;
                s_hook = 1;
            }
            __syncthreads();
            int hooked = s_hook;
            __syncthreads();
            if (!hooked) break;

            // flatten with early exit (uniform barriers)
            for (;;) {
                if (tid == 0) s_flag = 0;
                __syncthreads();
                for (int i = tid; i < nmin; i += NTHR) {
                    uint32_t p = par[i];
                    uint32_t g = par[p];
                    if (g != p) { par[i] = (uint16_t)g; s_flag = 1; }
                }
                __syncthreads();
                int f = s_flag;
                __syncthreads();
                if (!f) break;
            }

            // relabel + compact surviving (still-crossing) edges into dst.
            // Uniform iteration count: all 32 lanes always reach the shuffles.
            const int iters = (mcur + NTHR - 1) >> 10;
            for (int k = 0; k < iters; k++) {
                int e = tid + (k << 10);
                unsigned long long rec = 0ull;
                int c = 0;
                if (e < mcur) {
                    unsigned long long E = src[e];
                    uint32_t lo = (uint32_t)E;
                    uint32_t cu = par[lo >> 16], cv = par[lo & 0xFFFFu];
                    if (cu != cv) {
                        rec = (E & 0xFFFFFFFF00000000ull)
                            | ((unsigned long long)cu << 16) | cv;
                        c = 1;
                    }
                }
                int pre = c;
                #pragma unroll
                for (int o = 1; o < 32; o <<= 1) {
                    int n = __shfl_up_sync(FULL, pre, o);
                    if (lane >= o) pre += n;
                }
                int total = __shfl_sync(FULL, pre, 31);
                int excl = pre - c;
                int bs = 0;
                if (lane == 31 && total > 0) bs = atomicAdd(&s_cnt2, total);
                bs = __shfl_sync(FULL, bs, 31);
                if (c) dst[bs + excl] = rec;
            }
            __syncthreads();
            mcur = s_cnt2;                         // uniform read; reset at top of
            { unsigned long long* t = src; src = dst; dst = t; }  // next round
            if (mcur == 0) break;
            __syncthreads();
        }
    }
    __syncthreads();
    const int m2 = s_mcnt;                        // == nmin - 1

    // ---- P6: 8x4-bit LSD radix sort of MST edges by death fbits (bits 32..63)
    {
        uint32_t* hist = (uint32_t*)sm;           // 64 KB (par/sel dead)
        const size_t off = (size_t)img * CAP;
        for (int pass = 0; pass < 8; pass++) {
            const unsigned long long* src = (pass & 1) ? g_mstB + off : g_mstA + off;
            unsigned long long*       dst = (pass & 1) ? g_mstA + off : g_mstB + off;
            const int shift = 32 + pass * 4;

            #pragma unroll
            for (int i = 0; i < 16; i++) hist[i * 1024 + tid] = 0;
            __syncthreads();

            const int bse = tid * 16;
            for (int j = 0; j < 16; j++) {
                int idx = bse + j;
                if (idx < m2) {
                    uint32_t d = (uint32_t)(src[idx] >> shift) & 15u;
                    hist[(d << 10) + tid]++;
                }
            }
            __syncthreads();

            const int sb = tid * 16;
            uint32_t sum = 0;
            #pragma unroll
            for (int i = 0; i < 16; i++) sum += hist[sb + i];
            uint32_t v = sum;
            #pragma unroll
            for (int o = 1; o < 32; o <<= 1) {
                uint32_t t = __shfl_up_sync(FULL, v, o);
                if (lane >= o) v += t;
            }
            if (lane == 31) warpsum[wid] = v;
            __syncthreads();
            if (wid == 0) {
                uint32_t w = warpsum[lane], wv = w;
                #pragma unroll
                for (int o = 1; o < 32; o <<= 1) {
                    uint32_t t = __shfl_up_sync(FULL, wv, o);
                    if (lane >= o) wv += t;
                }
                warpsum[lane] = wv - w;
            }
            __syncthreads();
            uint32_t run = (v - sum) + warpsum[wid];
            #pragma unroll
            for (int i = 0; i < 16; i++) { uint32_t t = hist[sb + i]; hist[sb + i] = run; run += t; }
            __syncthreads();

            for (int j = 0; j < 16; j++) {
                int idx = bse + j;
                if (idx < m2) {
                    unsigned long long k = src[idx];
                    uint32_t d = (uint32_t)(k >> shift) & 15u;
                    dst[hist[(d << 10) + tid]++] = k;
                }
            }
            __syncthreads();
        }
    }

    // ---- P7: warp-parallel Kruskal pairing, chain-free commit-set evaluation.
    // Rule (proven order-equivalent): lane j blocked iff exists earlier active
    // lane l with (die_l in {ru_j, rv_j}) OR (blocked_l AND share(l, j)).
    // Phase A computes die-hits with an independent (pipelined) shuffle loop;
    // Phase B propagates blocking to a ballot fixpoint (typically 1 pass).
    // First active lane is never blocked -> guaranteed progress per round.
    {
        uint16_t* par = (uint16_t*)sm;
        uint32_t* birth = (uint32_t*)(sm + BIRTH_OFF);
        unsigned long long* mste = (unsigned long long*)(sm + MSTE_OFF);
        float* life = (float*)(sm + MSTE_OFF);   // overlays consumed mste prefix
        for (int i = tid; i < nmin; i += NTHR) {
            par[i] = (uint16_t)i;
            birth[i] = g_birth[(size_t)img * CAP + i];
        }
        for (int i = tid; i < m2; i += NTHR) mste[i] = g_mstA[(size_t)img * CAP + i];
        __syncthreads();

        if (tid < 32) {
            for (int bs0 = 0; bs0 < m2; bs0 += 32) {   // uniform trip count
                int j = bs0 + lane;
                bool have = j < m2;
                unsigned long long e = have ? mste[j] : 0ull;   // read BEFORE life writes
                uint32_t cu = (uint32_t)(e >> 16) & 0xFFFFu;
                uint32_t cv = (uint32_t)e & 0xFFFFu;
                float death = __uint_as_float((uint32_t)(e >> 32));
                bool done = !have;

                for (;;) {
                    unsigned pend = __ballot_sync(FULL, !done);
                    if (!pend) break;

                    // roots (sentinels for finished lanes keep comparisons false)
                    uint32_t ru, rv, die = 0xFFFFFFFFu, keep = 0;
                    if (!done) {
                        ru = uf_find(par, cu);
                        rv = uf_find(par, cv);
                        uint32_t bu = birth[ru], bv = birth[rv];
                        bool ku = (bu < bv) || (bu == bv && ru < rv);  // elder survives
                        keep = ku ? ru : rv;
                        die  = ku ? rv : ru;
                    } else {
                        ru = 0x20000u + lane * 2;
                        rv = ru + 1;
                    }
                    __syncwarp();

                    // Phase A: die-hit blocking (independent steps, no chain)
                    bool blk = false;
                    #pragma unroll
                    for (int l = 0; l < 31; l++) {
                        uint32_t dl = __shfl_sync(FULL, die, l);
                        if (lane > l && !done && (dl == ru || dl == rv)) blk = true;
                    }

                    // Phase B: propagate (blocked & share) to fixpoint
                    unsigned bm = __ballot_sync(FULL, !done && blk);
                    for (;;) {
                        bool nblk = blk;
                        #pragma unroll
                        for (int l = 0; l < 31; l++) {
                            uint32_t rul = __shfl_sync(FULL, ru, l);
                            uint32_t rvl = __shfl_sync(FULL, rv, l);
                            if (lane > l && !done && ((bm >> l) & 1u) &&
                                (rul == ru || rul == rv || rvl == ru || rvl == rv))
                                nblk = true;
                        }
                        unsigned nbm = __ballot_sync(FULL, !done && nblk);
                        blk = nblk;
                        if (nbm == bm) break;
                        bm = nbm;
                    }

                    // parallel commit of the safe set
                    if (!done && !blk) {
                        par[die] = (uint16_t)keep;
                        life[j] = death - __uint_as_float(birth[die]);
                        done = true;
                    }
                    __syncwarp();
                }
            }
        }
        __syncthreads();

        // ---- P8: top-5 via per-thread regs -> warp shuffle merge -> tiny scan
        float t0 = -1e30f, t1 = -1e30f, t2 = -1e30f, t3 = -1e30f, t4 = -1e30f;
        for (int i = tid; i < m2; i += NTHR) top5_ins(t0, t1, t2, t3, t4, life[i]);
        #pragma unroll
        for (int o = 16; o > 0; o >>= 1) {
            float a0 = __shfl_down_sync(FULL, t0, o);
            float a1 = __shfl_down_sync(FULL, t1, o);
            float a2 = __shfl_down_sync(FULL, t2, o);
            float a3 = __shfl_down_sync(FULL, t3, o);
            float a4 = __shfl_down_sync(FULL, t4, o);
            top5_ins(t0, t1, t2, t3, t4, a0);
            top5_ins(t0, t1, t2, t3, t4, a1);
            top5_ins(t0, t1, t2, t3, t4, a2);
            top5_ins(t0, t1, t2, t3, t4, a3);
            top5_ins(t0, t1, t2, t3, t4, a4);
        }
        if (lane == 0) {
            cand2[wid * 5 + 0] = t0; cand2[wid * 5 + 1] = t1; cand2[wid * 5 + 2] = t2;
            cand2[wid * 5 + 3] = t3; cand2[wid * 5 + 4] = t4;
        }
        __syncthreads();
        if (tid == 0) {
            float s0 = -1e30f, s1 = -1e30f, s2 = -1e30f, s3 = -1e30f, s4 = -1e30f;
            for (int i = 0; i < 32 * 5; i++) top5_ins(s0, s1, s2, s3, s4, cand2[i]);
            if (s0 < -1e29f) s0 = 0.0f;        // pad with 0-life pairs
            if (s1 < -1e29f) s1 = 0.0f;
            if (s2 < -1e29f) s2 = 0.0f;
            if (s3 < -1e29f) s3 = 0.0f;
            if (s4 < -1e29f) s4 = 0.0f;
            float d0 = s0 - 0.5f, d1 = s1 - 0.5f, d2 = s2 - 0.5f, d3 = s3 - 0.5f, d4 = s4 - 0.5f;
            g_loss[img] = (d0 * d0 + d1 * d1 + d2 * d2 + d3 * d3 + d4 * d4) * 0.2f;

            // ---- fused final reduction: last block to arrive sums the losses
            __threadfence();
            int old = atomicAdd(&g_done, 1);
            if (old == NIMG - 1) {
                __threadfence();
                out[0] = (g_loss[0] + g_loss[1] + g_loss[2] + g_loss[3]) * 25.0f;
                g_done = 0;                    // reset for next graph replay
            }
        }
    }
}

// ---------------- launch -----------------------------------------------------
extern "C" void kernel_launch(void* const* d_in, const int* in_sizes, int n_in,
                              void* d_out, int out_size) {
    (void)in_sizes; (void)n_in; (void)out_size;
    const float* prob = (const float*)d_in[0];
    const float* roi  = (const float*)d_in[1];
    float* out = (float*)d_out;

    cudaFuncSetAttribute(k_fused, cudaFuncAttributeMaxDynamicSharedMemorySize, SMEM_BYTES);

    k_fused<<<NIMG, NTHR, SMEM_BYTES>>>(prob, roi, out);
}

// round 16
// speedup vs baseline: 1.5344x; 1.0023x over previous
#include <cuda_runtime.h>
#include <stdint.h>

#define NPIX 65536
#define NIMG 4
#define EMAX 131072            // >= 2*256*255 grid edges per image
#define CAP  16384             // minima cap (expected ~13.1k for this data)
#define NTHR 1024

// dynamic smem layout (phase overlays), total 229376 B <= 227KB limit
#define SEL_OFF    32768       // Boruvka: par u16[CAP] @0, sel u64[CAP] @32768 (ends 163840)
#define BIRTH_OFF  32768       // pairing: par u16[CAP] @0, birth u32[CAP] @32768
#define MSTE_OFF   98304       // pairing: mst u64[CAP] @98304 (ends 229376); life f32 overlays
#define SMEM_BYTES 229376

// ---------------- device scratch (no allocations allowed) -------------------
__device__ uint32_t           g_fbits[NIMG * NPIX];
__device__ unsigned long long g_edges[NIMG * EMAX];
__device__ unsigned long long g_edgesB[NIMG * EMAX];
__device__ unsigned long long g_mstA[NIMG * CAP];
__device__ unsigned long long g_mstB[NIMG * CAP];
__device__ uint32_t           g_birth[NIMG * CAP];
__device__ float              g_loss[NIMG];
__device__ int                g_done;              // static-zero; reset by last block

__device__ __forceinline__ uint32_t uf_find(uint16_t* par, uint32_t x) {
    uint32_t p = par[x];
    while (p != x) {                     // path halving
        uint32_t g = par[p];
        par[x] = (uint16_t)g;
        x = g;
        p = par[x];
    }
    return x;
}

__device__ __forceinline__ void top5_ins(float& t0, float& t1, float& t2,
                                         float& t3, float& t4, float life) {
    if (life <= t4) return;
    if (life > t0)      { t4 = t3; t3 = t2; t2 = t1; t1 = t0; t0 = life; }
    else if (life > t1) { t4 = t3; t3 = t2; t2 = t1; t1 = life; }
    else if (life > t2) { t4 = t3; t3 = t2; t2 = life; }
    else if (life > t3) { t4 = t3; t3 = life; }
    else                  t4 = life;
}

// =============================================================================
// One block per image: the entire PH-0 pipeline with shared-memory overlays.
// =============================================================================
__global__ void __launch_bounds__(NTHR, 1)
k_fused(const float* __restrict__ prob, const float* __restrict__ roi,
        float* __restrict__ out) {
    extern __shared__ char sm[];
    __shared__ uint32_t warpsum[32];
    __shared__ float cand2[32 * 5];
    __shared__ int s_flag, s_hook, s_ecnt, s_mcnt, s_nmin, s_cnt2;

    const int img  = blockIdx.x;
    const int tid  = threadIdx.x;
    const int lane = tid & 31;
    const int wid  = tid >> 5;
    const unsigned FULL = 0xFFFFFFFFu;

    uint32_t* fb = g_fbits + (size_t)img * NPIX;
    uint16_t* B  = (uint16_t*)sm;                 // pixel->parent / basin / dense id

    if (tid == 0) { s_ecnt = 0; s_mcnt = 0; }

    // ---- P0: f = 1 - prob*roi, store float bits (f>0 -> bit order == order)
    for (int i = tid; i < NPIX; i += NTHR) {
        int gi = img * NPIX + i;
        fb[i] = __float_as_uint(1.0f - prob[gi] * roi[gi]);
    }
    __syncthreads();

    // ---- P1: steepest-descent parent by key (fbits, pix)
    for (int i = tid; i < NPIX; i += NTHR) {
        unsigned long long k0 = ((unsigned long long)fb[i] << 16) | (unsigned)i;
        int y = i >> 8, x = i & 255;
        unsigned long long kb = ~0ull;
        if (y > 0)   { unsigned long long k = ((unsigned long long)fb[i-256] << 16) | (unsigned)(i-256); if (k < kb) kb = k; }
        if (y < 255) { unsigned long long k = ((unsigned long long)fb[i+256] << 16) | (unsigned)(i+256); if (k < kb) kb = k; }
        if (x > 0)   { unsigned long long k = ((unsigned long long)fb[i-1]   << 16) | (unsigned)(i-1);   if (k < kb) kb = k; }
        if (x < 255) { unsigned long long k = ((unsigned long long)fb[i+1]   << 16) | (unsigned)(i+1);   if (k < kb) kb = k; }
        B[i] = (kb < k0) ? (uint16_t)(kb & 0xFFFFu) : (uint16_t)i;
    }
    __syncthreads();

    // ---- P2: pointer doubling to basin roots, early exit (uniform barriers)
    for (;;) {
        if (tid == 0) s_flag = 0;
        __syncthreads();
        for (int i = tid; i < NPIX; i += NTHR) {
            uint32_t p = B[i];
            uint32_t g = B[p];
            if (g != p) { B[i] = (uint16_t)g; s_flag = 1; }
        }
        __syncthreads();
        int f = s_flag;
        __syncthreads();
        if (!f) break;
    }

    // ---- P3: dense minima ids (pixel order) + birth fbits; rewrite B -> dense
    const int chbase = tid * 64;
    unsigned long long rootmask = 0ull;
    uint32_t cnt = 0;
    for (int j = 0; j < 64; j++) {
        if (B[chbase + j] == (uint16_t)(chbase + j)) { rootmask |= 1ull << j; cnt++; }
    }
    {   // block exclusive scan of cnt (thread-chunk order; uniform trip count)
        uint32_t v = cnt;
        #pragma unroll
        for (int o = 1; o < 32; o <<= 1) {
            uint32_t n = __shfl_up_sync(FULL, v, o);
            if (lane >= o) v += n;
        }
        if (lane == 31) warpsum[wid] = v;
        __syncthreads();
        if (wid == 0) {
            uint32_t w = warpsum[lane], wv = w;
            #pragma unroll
            for (int o = 1; o < 32; o <<= 1) {
                uint32_t n = __shfl_up_sync(FULL, wv, o);
                if (lane >= o) wv += n;
            }
            warpsum[lane] = wv - w;
        }
        __syncthreads();
        uint32_t run = (v - cnt) + warpsum[wid];
        if (tid == NTHR - 1) s_nmin = (int)(run + cnt);
        // step b: roots get dense id; record birth fbits
        uint32_t r = run;
        for (int j = 0; j < 64; j++) {
            if ((rootmask >> j) & 1ull) {
                int i = chbase + j;
                g_birth[(size_t)img * CAP + r] = fb[i];
                B[i] = (uint16_t)r;
                r++;
            }
        }
    }
    __syncthreads();
    // step c: non-roots: B[i] = dense(B_old[i]) (root entries already dense)
    for (int j = 0; j < 64; j++) {
        if (!((rootmask >> j) & 1ull)) {
            int i = chbase + j;
            B[i] = B[B[i]];
        }
    }
    __syncthreads();
    const int nmin = s_nmin;

    // ---- P4: crossing edges (right/down), record (death_fbits | cu | cv)
    // NPIX is a multiple of NTHR -> warp shuffles always fully converged.
    unsigned long long* ed  = g_edges  + (size_t)img * EMAX;
    unsigned long long* edB = g_edgesB + (size_t)img * EMAX;
    for (int i = tid; i < NPIX; i += NTHR) {
        uint32_t f0 = fb[i];
        uint32_t cu = B[i];
        int y = i >> 8, x = i & 255;
        unsigned long long recs[2];
        int c = 0;
        if (x < 255) {
            uint32_t cv = B[i + 1];
            if (cv != cu) {
                uint32_t f1 = fb[i + 1];
                uint32_t d = f0 > f1 ? f0 : f1;
                recs[c++] = ((unsigned long long)d << 32) | ((unsigned long long)cu << 16) | cv;
            }
        }
        if (y < 255) {
            uint32_t cv = B[i + 256];
            if (cv != cu) {
                uint32_t f1 = fb[i + 256];
                uint32_t d = f0 > f1 ? f0 : f1;
                recs[c++] = ((unsigned long long)d << 32) | ((unsigned long long)cu << 16) | cv;
            }
        }
        int pre = c;
        #pragma unroll
        for (int o = 1; o < 32; o <<= 1) {
            int n = __shfl_up_sync(FULL, pre, o);
            if (lane >= o) pre += n;
        }
        int total = __shfl_sync(FULL, pre, 31);
        int excl = pre - c;
        int bs = 0;
        if (lane == 31 && total > 0) bs = atomicAdd(&s_ecnt, total);
        bs = __shfl_sync(FULL, bs, 31);
        for (int j = 0; j < c; j++) ed[bs + excl + j] = recs[j];
    }
    __syncthreads();

    // ---- P5: Boruvka MST, per-round edge compaction (ping-pong gmem)
    {
        uint16_t* par = (uint16_t*)sm;
        unsigned long long* sel = (unsigned long long*)(sm + SEL_OFF);
        unsigned long long* mst = g_mstA + (size_t)img * CAP;
        unsigned long long* src = ed;
        unsigned long long* dst = edB;
        int mcur = s_ecnt;
        for (int i = tid; i < nmin; i += NTHR) par[i] = (uint16_t)i;

        for (int round = 0; round < 24; round++) {
            if (tid == 0) { s_hook = 0; s_cnt2 = 0; }
            for (int i = tid; i < nmin; i += NTHR) sel[i] = ~0ull;
            __syncthreads();

            // lightest external edge per component: key=(fb<<16)|other.
            // READ-BEFORE-ATOMIC: sel[] is monotonically non-increasing, so a
            // plain LDS.64 read (atomic at 8B) filters hopeless candidates:
            // stale-high read -> redundant-but-correct atomic; low read proves
            // the candidate cannot win. Cuts ATOMS traffic ~O(deg)->O(log deg).
            for (int e = tid; e < mcur; e += NTHR) {
                unsigned long long E = src[e];
                uint32_t lo = (uint32_t)E;
                uint32_t cu = lo >> 16, cv = lo & 0xFFFFu;
                unsigned long long fbw = E >> 32;
                unsigned long long keyu = (fbw << 16) | cv;
                unsigned long long keyv = (fbw << 16) | cu;
                if (sel[cu] > keyu) atomicMin(&sel[cu], keyu);
                if (sel[cv] > keyv) atomicMin(&sel[cv], keyv);
            }
            __syncthreads();

            // hook (mutual 2-cycles: smaller id stays root) + record MST edge
            for (int c = tid; c < nmin; c += NTHR) {
                unsigned long long s = sel[c];
                if (s == ~0ull) continue;
                uint32_t d = (uint32_t)(s & 0xFFFFu);
                unsigned long long sd = sel[d];
                bool mutual = ((uint32_t)(sd & 0xFFFFu) == (uint32_t)c);
                if (mutual && (uint32_t)c < d) continue;
                par[c] = (uint16_t)d;
                int pos = atomicAdd(&s_mcnt, 1);
                mst[pos] = ((s >> 16) << 32) | ((unsigned long long)c << 16) | d;
                s_hook = 1;
            }
            __syncthreads();
            int hooked = s_hook;
            __syncthreads();
            if (!hooked) break;

            // flatten with early exit (uniform barriers)
            for (;;) {
                if (tid == 0) s_flag = 0;
                __syncthreads();
                for (int i = tid; i < nmin; i += NTHR) {
                    uint32_t p = par[i];
                    uint32_t g = par[p];
                    if (g != p) { par[i] = (uint16_t)g; s_flag = 1; }
                }
                __syncthreads();
                int f = s_flag;
                __syncthreads();
                if (!f) break;
            }

            // relabel + compact surviving (still-crossing) edges into dst.
            // Uniform iteration count: all 32 lanes always reach the shuffles.
            const int iters = (mcur + NTHR - 1) >> 10;
            for (int k = 0; k < iters; k++) {
                int e = tid + (k << 10);
                unsigned long long rec = 0ull;
                int c = 0;
                if (e < mcur) {
                    unsigned long long E = src[e];
                    uint32_t lo = (uint32_t)E;
                    uint32_t cu = par[lo >> 16], cv = par[lo & 0xFFFFu];
                    if (cu != cv) {
                        rec = (E & 0xFFFFFFFF00000000ull)
                            | ((unsigned long long)cu << 16) | cv;
                        c = 1;
                    }
                }
                int pre = c;
                #pragma unroll
                for (int o = 1; o < 32; o <<= 1) {
                    int n = __shfl_up_sync(FULL, pre, o);
                    if (lane >= o) pre += n;
                }
                int total = __shfl_sync(FULL, pre, 31);
                int excl = pre - c;
                int bs = 0;
                if (lane == 31 && total > 0) bs = atomicAdd(&s_cnt2, total);
                bs = __shfl_sync(FULL, bs, 31);
                if (c) dst[bs + excl] = rec;
            }
            __syncthreads();
            mcur = s_cnt2;                         // uniform read; reset at top of
            { unsigned long long* t = src; src = dst; dst = t; }  // next round
            if (mcur == 0) break;
            __syncthreads();
        }
    }
    __syncthreads();
    const int m2 = s_mcnt;                        // == nmin - 1

    // ---- P6: 8x4-bit LSD radix sort of MST edges by death fbits (bits 32..63)
    {
        uint32_t* hist = (uint32_t*)sm;           // 64 KB (par/sel dead)
        const size_t off = (size_t)img * CAP;
        for (int pass = 0; pass < 8; pass++) {
            const unsigned long long* src = (pass & 1) ? g_mstB + off : g_mstA + off;
            unsigned long long*       dst = (pass & 1) ? g_mstA + off : g_mstB + off;
            const int shift = 32 + pass * 4;

            #pragma unroll
            for (int i = 0; i < 16; i++) hist[i * 1024 + tid] = 0;
            __syncthreads();

            const int bse = tid * 16;
            for (int j = 0; j < 16; j++) {
                int idx = bse + j;
                if (idx < m2) {
                    uint32_t d = (uint32_t)(src[idx] >> shift) & 15u;
                    hist[(d << 10) + tid]++;
                }
            }
            __syncthreads();

            const int sb = tid * 16;
            uint32_t sum = 0;
            #pragma unroll
            for (int i = 0; i < 16; i++) sum += hist[sb + i];
            uint32_t v = sum;
            #pragma unroll
            for (int o = 1; o < 32; o <<= 1) {
                uint32_t t = __shfl_up_sync(FULL, v, o);
                if (lane >= o) v += t;
            }
            if (lane == 31) warpsum[wid] = v;
            __syncthreads();
            if (wid == 0) {
                uint32_t w = warpsum[lane], wv = w;
                #pragma unroll
                for (int o = 1; o < 32; o <<= 1) {
                    uint32_t t = __shfl_up_sync(FULL, wv, o);
                    if (lane >= o) wv += t;
                }
                warpsum[lane] = wv - w;
            }
            __syncthreads();
            uint32_t run = (v - sum) + warpsum[wid];
            #pragma unroll
            for (int i = 0; i < 16; i++) { uint32_t t = hist[sb + i]; hist[sb + i] = run; run += t; }
            __syncthreads();

            for (int j = 0; j < 16; j++) {
                int idx = bse + j;
                if (idx < m2) {
                    unsigned long long k = src[idx];
                    uint32_t d = (uint32_t)(k >> shift) & 15u;
                    dst[hist[(d << 10) + tid]++] = k;
                }
            }
            __syncthreads();
        }
    }

    // ---- P7: warp-parallel Kruskal pairing, chain-free commit-set evaluation.
    // Rule (proven order-equivalent): lane j blocked iff exists earlier active
    // lane l with (die_l in {ru_j, rv_j}) OR (blocked_l AND share(l, j)).
    // Phase A computes die-hits with an independent (pipelined) shuffle loop;
    // Phase B propagates blocking to a ballot fixpoint (typically 1 pass).
    // First active lane is never blocked -> guaranteed progress per round.
    {
        uint16_t* par = (uint16_t*)sm;
        uint32_t* birth = (uint32_t*)(sm + BIRTH_OFF);
        unsigned long long* mste = (unsigned long long*)(sm + MSTE_OFF);
        float* life = (float*)(sm + MSTE_OFF);   // overlays consumed mste prefix
        for (int i = tid; i < nmin; i += NTHR) {
            par[i] = (uint16_t)i;
            birth[i] = g_birth[(size_t)img * CAP + i];
        }
        for (int i = tid; i < m2; i += NTHR) mste[i] = g_mstA[(size_t)img * CAP + i];
        __syncthreads();

        if (tid < 32) {
            for (int bs0 = 0; bs0 < m2; bs0 += 32) {   // uniform trip count
                int j = bs0 + lane;
                bool have = j < m2;
                unsigned long long e = have ? mste[j] : 0ull;   // read BEFORE life writes
                uint32_t cu = (uint32_t)(e >> 16) & 0xFFFFu;
                uint32_t cv = (uint32_t)e & 0xFFFFu;
                float death = __uint_as_float((uint32_t)(e >> 32));
                bool done = !have;

                for (;;) {
                    unsigned pend = __ballot_sync(FULL, !done);
                    if (!pend) break;

                    // roots (sentinels for finished lanes keep comparisons false)
                    uint32_t ru, rv, die = 0xFFFFFFFFu, keep = 0;
                    if (!done) {
                        ru = uf_find(par, cu);
                        rv = uf_find(par, cv);
                        uint32_t bu = birth[ru], bv = birth[rv];
                        bool ku = (bu < bv) || (bu == bv && ru < rv);  // elder survives
                        keep = ku ? ru : rv;
                        die  = ku ? rv : ru;
                    } else {
                        ru = 0x20000u + lane * 2;
                        rv = ru + 1;
                    }
                    __syncwarp();

                    // Phase A: die-hit blocking (independent steps, no chain)
                    bool blk = false;
                    #pragma unroll
                    for (int l = 0; l < 31; l++) {
                        uint32_t dl = __shfl_sync(FULL, die, l);
                        if (lane > l && !done && (dl == ru || dl == rv)) blk = true;
                    }

                    // Phase B: propagate (blocked & share) to fixpoint
                    unsigned bm = __ballot_sync(FULL, !done && blk);
                    for (;;) {
                        bool nblk = blk;
                        #pragma unroll
                        for (int l = 0; l < 31; l++) {
                            uint32_t rul = __shfl_sync(FULL, ru, l);
                            uint32_t rvl = __shfl_sync(FULL, rv, l);
                            if (lane > l && !done && ((bm >> l) & 1u) &&
                                (rul == ru || rul == rv || rvl == ru || rvl == rv))
                                nblk = true;
                        }
                        unsigned nbm = __ballot_sync(FULL, !done && nblk);
                        blk = nblk;
                        if (nbm == bm) break;
                        bm = nbm;
                    }

                    // parallel commit of the safe set
                    if (!done && !blk) {
                        par[die] = (uint16_t)keep;
                        life[j] = death - __uint_as_float(birth[die]);
                        done = true;
                    }
                    __syncwarp();
                }
            }
        }
        __syncthreads();

        // ---- P8: top-5 via per-thread regs -> warp shuffle merge -> tiny scan
        float t0 = -1e30f, t1 = -1e30f, t2 = -1e30f, t3 = -1e30f, t4 = -1e30f;
        for (int i = tid; i < m2; i += NTHR) top5_ins(t0, t1, t2, t3, t4, life[i]);
        #pragma unroll
        for (int o = 16; o > 0; o >>= 1) {
            float a0 = __shfl_down_sync(FULL, t0, o);
            float a1 = __shfl_down_sync(FULL, t1, o);
            float a2 = __shfl_down_sync(FULL, t2, o);
            float a3 = __shfl_down_sync(FULL, t3, o);
            float a4 = __shfl_down_sync(FULL, t4, o);
            top5_ins(t0, t1, t2, t3, t4, a0);
            top5_ins(t0, t1, t2, t3, t4, a1);
            top5_ins(t0, t1, t2, t3, t4, a2);
            top5_ins(t0, t1, t2, t3, t4, a3);
            top5_ins(t0, t1, t2, t3, t4, a4);
        }
        if (lane == 0) {
            cand2[wid * 5 + 0] = t0; cand2[wid * 5 + 1] = t1; cand2[wid * 5 + 2] = t2;
            cand2[wid * 5 + 3] = t3; cand2[wid * 5 + 4] = t4;
        }
        __syncthreads();
        if (tid == 0) {
            float s0 = -1e30f, s1 = -1e30f, s2 = -1e30f, s3 = -1e30f, s4 = -1e30f;
            for (int i = 0; i < 32 * 5; i++) top5_ins(s0, s1, s2, s3, s4, cand2[i]);
            if (s0 < -1e29f) s0 = 0.0f;        // pad with 0-life pairs
            if (s1 < -1e29f) s1 = 0.0f;
            if (s2 < -1e29f) s2 = 0.0f;
            if (s3 < -1e29f) s3 = 0.0f;
            if (s4 < -1e29f) s4 = 0.0f;
            float d0 = s0 - 0.5f, d1 = s1 - 0.5f, d2 = s2 - 0.5f, d3 = s3 - 0.5f, d4 = s4 - 0.5f;
            g_loss[img] = (d0 * d0 + d1 * d1 + d2 * d2 + d3 * d3 + d4 * d4) * 0.2f;

            // ---- fused final reduction: last block to arrive sums the losses
            __threadfence();
            int old = atomicAdd(&g_done, 1);
            if (old == NIMG - 1) {
                __threadfence();
                out[0] = (g_loss[0] + g_loss[1] + g_loss[2] + g_loss[3]) * 25.0f;
                g_done = 0;                    // reset for next graph replay
            }
        }
    }
}

// ---------------- launch -----------------------------------------------------
extern "C" void kernel_launch(void* const* d_in, const int* in_sizes, int n_in,
                              void* d_out, int out_size) {
    (void)in_sizes; (void)n_in; (void)out_size;
    const float* prob = (const float*)d_in[0];
    const float* roi  = (const float*)d_in[1];
    float* out = (float*)d_out;

    cudaFuncSetAttribute(k_fused, cudaFuncAttributeMaxDynamicSharedMemorySize, SMEM_BYTES);

    k_fused<<<NIMG, NTHR, SMEM_BYTES>>>(prob, roi, out);
}

// round 17
// speedup vs baseline: 1.7062x; 1.1119x over previous
#include <cuda_runtime.h>
#include <stdint.h>

#define NPIX 65536
#define NIMG 4
#define EMAX 131072            // >= 2*256*255 grid edges per image
#define CAP  16384             // minima cap (expected ~13.1k for this data)
#define NTHR 1024
#define NBLK ((NIMG * NPIX) / NTHR)   // 256 blocks, 64 per image

// ---------------- device scratch (no allocations allowed) -------------------
__device__ uint32_t           g_fbits[NIMG * NPIX];
__device__ uint16_t           g_desc[NIMG * NPIX];    // steepest-descent parent
__device__ uint16_t           g_bas[NIMG * NPIX];     // basin root pixel
__device__ uint16_t           g_dtab[NIMG * NPIX];    // root pixel -> dense id
__device__ uint32_t           g_birth[NIMG * CAP];
__device__ int                g_nmin[NIMG];
__device__ unsigned long long g_edges[NIMG * EMAX];
__device__ unsigned long long g_edgesB[NIMG * EMAX];
__device__ int                g_ecnt[NIMG];
__device__ unsigned long long g_mstA[NIMG * CAP];
__device__ unsigned long long g_mstB[NIMG * CAP];
__device__ int                g_mcnt[NIMG];
__device__ float              g_loss[NIMG];
__device__ int                g_done;                 // static-zero; self-resets

__device__ __forceinline__ uint32_t uf_find(uint16_t* par, uint32_t x) {
    uint32_t p = par[x];
    while (p != x) {                     // path halving
        uint32_t g = par[p];
        par[x] = (uint16_t)g;
        x = g;
        p = par[x];
    }
    return x;
}

__device__ __forceinline__ void top5_ins(float& t0, float& t1, float& t2,
                                         float& t3, float& t4, float life) {
    if (life <= t4) return;
    if (life > t0)      { t4 = t3; t3 = t2; t2 = t1; t1 = t0; t0 = life; }
    else if (life > t1) { t4 = t3; t3 = t2; t2 = t1; t1 = life; }
    else if (life > t2) { t4 = t3; t3 = t2; t2 = life; }
    else if (life > t3) { t4 = t3; t3 = life; }
    else                  t4 = life;
}

// ---------------- k1: f bits + counter reset (full chip) --------------------
__global__ void k_init(const float* __restrict__ prob, const float* __restrict__ roi) {
    int i = blockIdx.x * NTHR + threadIdx.x;
    g_fbits[i] = __float_as_uint(1.0f - prob[i] * roi[i]);  // f>0: bit order == order
    if (i < NIMG) { g_ecnt[i] = 0; g_mcnt[i] = 0; }
}

// ---------------- k2: steepest-descent parent by key (fbits, pix) -----------
__global__ void k_desc() {
    int i = blockIdx.x * NTHR + threadIdx.x;
    int img = i >> 16;
    uint32_t p = (uint32_t)(i & (NPIX - 1));
    const uint32_t* fb = g_fbits + ((size_t)img << 16);
    unsigned long long k0 = ((unsigned long long)fb[p] << 16) | p;
    int y = p >> 8, x = p & 255;
    unsigned long long kb = ~0ull;
    if (y > 0)   { unsigned long long k = ((unsigned long long)fb[p-256] << 16) | (p-256); if (k < kb) kb = k; }
    if (y < 255) { unsigned long long k = ((unsigned long long)fb[p+256] << 16) | (p+256); if (k < kb) kb = k; }
    if (x > 0)   { unsigned long long k = ((unsigned long long)fb[p-1]   << 16) | (p-1);   if (k < kb) kb = k; }
    if (x < 255) { unsigned long long k = ((unsigned long long)fb[p+1]   << 16) | (p+1);   if (k < kb) kb = k; }
    g_desc[i] = (kb < k0) ? (uint16_t)(kb & 0xFFFFu) : (uint16_t)p;
}

// ---------------- k3: walk to basin root (read-only forest, full chip) ------
__global__ void k_walk() {
    int i = blockIdx.x * NTHR + threadIdx.x;
    int img = i >> 16;
    const uint16_t* __restrict__ D = g_desc + ((size_t)img << 16);
    uint32_t x = D[i & (NPIX - 1)];
    uint32_t p = D[x];
    while (p != x) { x = p; p = D[x]; }
    g_bas[i] = (uint16_t)x;
}

// ---------------- k4: dense minima ids in PIXEL ORDER (elder tie-break) -----
__global__ void __launch_bounds__(NTHR, 1) k_dense() {
    __shared__ uint32_t warpsum[32];
    const int img = blockIdx.x, tid = threadIdx.x;
    const int lane = tid & 31, wid = tid >> 5;
    const unsigned FULL = 0xFFFFFFFFu;
    const uint16_t* D = g_desc + ((size_t)img << 16);
    const uint32_t* fb = g_fbits + ((size_t)img << 16);
    const int chbase = tid * 64;

    unsigned long long rootmask = 0ull;
    uint32_t cnt = 0;
    for (int j = 0; j < 64; j++) {
        if (D[chbase + j] == (uint16_t)(chbase + j)) { rootmask |= 1ull << j; cnt++; }
    }
    uint32_t v = cnt;
    #pragma unroll
    for (int o = 1; o < 32; o <<= 1) {
        uint32_t n = __shfl_up_sync(FULL, v, o);
        if (lane >= o) v += n;
    }
    if (lane == 31) warpsum[wid] = v;
    __syncthreads();
    if (wid == 0) {
        uint32_t w = warpsum[lane], wv = w;
        #pragma unroll
        for (int o = 1; o < 32; o <<= 1) {
            uint32_t n = __shfl_up_sync(FULL, wv, o);
            if (lane >= o) wv += n;
        }
        warpsum[lane] = wv - w;
    }
    __syncthreads();
    uint32_t run = (v - cnt) + warpsum[wid];
    if (tid == NTHR - 1) g_nmin[img] = (int)(run + cnt);
    uint16_t* dt = g_dtab + ((size_t)img << 16);
    for (int j = 0; j < 64; j++) {
        if ((rootmask >> j) & 1ull) {
            int i = chbase + j;
            g_birth[(size_t)img * CAP + run] = fb[i];
            dt[i] = (uint16_t)run;
            run++;
        }
    }
}

// ---------------- k5: crossing edges (full chip, warp-agg global append) ----
__global__ void k_edges() {
    int i = blockIdx.x * NTHR + threadIdx.x;
    int img = i >> 16;
    uint32_t p = (uint32_t)(i & (NPIX - 1));
    const int lane = threadIdx.x & 31;
    const unsigned FULL = 0xFFFFFFFFu;
    const uint32_t* fb = g_fbits + ((size_t)img << 16);
    const uint16_t* bs = g_bas   + ((size_t)img << 16);
    const uint16_t* dt = g_dtab  + ((size_t)img << 16);

    uint32_t f0 = fb[p];
    uint32_t b0 = bs[p];
    int y = p >> 8, x = p & 255;
    unsigned long long recs[2];
    int c = 0;
    if (x < 255) {
        uint32_t b1 = bs[p + 1];
        if (b1 != b0) {
            uint32_t f1 = fb[p + 1];
            uint32_t d = f0 > f1 ? f0 : f1;
            recs[c++] = ((unsigned long long)d << 32)
                      | ((unsigned long long)dt[b0] << 16) | dt[b1];
        }
    }
    if (y < 255) {
        uint32_t b1 = bs[p + 256];
        if (b1 != b0) {
            uint32_t f1 = fb[p + 256];
            uint32_t d = f0 > f1 ? f0 : f1;
            recs[c++] = ((unsigned long long)d << 32)
                      | ((unsigned long long)dt[b0] << 16) | dt[b1];
        }
    }
    // warp-aggregated append (all 32 lanes present: 1 pixel per thread)
    int pre = c;
    #pragma unroll
    for (int o = 1; o < 32; o <<= 1) {
        int n = __shfl_up_sync(FULL, pre, o);
        if (lane >= o) pre += n;
    }
    int total = __shfl_sync(FULL, pre, 31);
    int excl = pre - c;
    int bsx = 0;
    if (lane == 31 && total > 0) bsx = atomicAdd(&g_ecnt[img], total);
    bsx = __shfl_sync(FULL, bsx, 31);
    unsigned long long* er = g_edges + (size_t)img * EMAX;
    for (int j = 0; j < c; j++) er[bsx + excl + j] = recs[j];
}

// ---------------- k6: Boruvka MST, per-round edge compaction ----------------
__global__ void __launch_bounds__(NTHR, 1) k_boruvka() {
    extern __shared__ char sm[];
    __shared__ int s_flag, s_hook, s_mcnt, s_cnt2;
    const int img = blockIdx.x, tid = threadIdx.x;
    const int lane = tid & 31;
    const unsigned FULL = 0xFFFFFFFFu;
    uint16_t* par = (uint16_t*)sm;                       // 32 KB
    unsigned long long* sel = (unsigned long long*)(sm + 32768);  // 128 KB
    unsigned long long* mst = g_mstA + (size_t)img * CAP;
    unsigned long long* src = g_edges  + (size_t)img * EMAX;
    unsigned long long* dst = g_edgesB + (size_t)img * EMAX;
    const int nmin = g_nmin[img];
    int mcur = g_ecnt[img];
    if (tid == 0) s_mcnt = 0;
    for (int i = tid; i < nmin; i += NTHR) par[i] = (uint16_t)i;

    for (int round = 0; round < 24; round++) {
        if (tid == 0) { s_hook = 0; s_cnt2 = 0; }
        for (int i = tid; i < nmin; i += NTHR) sel[i] = ~0ull;
        __syncthreads();

        // lightest external edge per component (read-guarded atomicMin)
        for (int e = tid; e < mcur; e += NTHR) {
            unsigned long long E = src[e];
            uint32_t lo = (uint32_t)E;
            uint32_t cu = lo >> 16, cv = lo & 0xFFFFu;
            unsigned long long fbw = E >> 32;
            unsigned long long keyu = (fbw << 16) | cv;
            unsigned long long keyv = (fbw << 16) | cu;
            if (sel[cu] > keyu) atomicMin(&sel[cu], keyu);
            if (sel[cv] > keyv) atomicMin(&sel[cv], keyv);
        }
        __syncthreads();

        // hook (mutual 2-cycles: smaller id stays root) + record MST edge
        for (int c = tid; c < nmin; c += NTHR) {
            unsigned long long s = sel[c];
            if (s == ~0ull) continue;
            uint32_t d = (uint32_t)(s & 0xFFFFu);
            unsigned long long sd = sel[d];
            bool mutual = ((uint32_t)(sd & 0xFFFFu) == (uint32_t)c);
            if (mutual && (uint32_t)c < d) continue;
            par[c] = (uint16_t)d;
            int pos = atomicAdd(&s_mcnt, 1);
            mst[pos] = ((s >> 16) << 32) | ((unsigned long long)c << 16) | d;
            s_hook = 1;
        }
        __syncthreads();
        int hooked = s_hook;
        __syncthreads();
        if (!hooked) break;

        // flatten with early exit (uniform barriers)
        for (;;) {
            if (tid == 0) s_flag = 0;
            __syncthreads();
            for (int i = tid; i < nmin; i += NTHR) {
                uint32_t p = par[i];
                uint32_t g = par[p];
                if (g != p) { par[i] = (uint16_t)g; s_flag = 1; }
            }
            __syncthreads();
            int f = s_flag;
            __syncthreads();
            if (!f) break;
        }

        // relabel + compact; uniform trip count so shuffles never diverge
        const int iters = (mcur + NTHR - 1) >> 10;
        for (int k = 0; k < iters; k++) {
            int e = tid + (k << 10);
            unsigned long long rec = 0ull;
            int c = 0;
            if (e < mcur) {
                unsigned long long E = src[e];
                uint32_t lo = (uint32_t)E;
                uint32_t cu = par[lo >> 16], cv = par[lo & 0xFFFFu];
                if (cu != cv) {
                    rec = (E & 0xFFFFFFFF00000000ull)
                        | ((unsigned long long)cu << 16) | cv;
                    c = 1;
                }
            }
            int pre = c;
            #pragma unroll
            for (int o = 1; o < 32; o <<= 1) {
                int n = __shfl_up_sync(FULL, pre, o);
                if (lane >= o) pre += n;
            }
            int total = __shfl_sync(FULL, pre, 31);
            int excl = pre - c;
            int bs = 0;
            if (lane == 31 && total > 0) bs = atomicAdd(&s_cnt2, total);
            bs = __shfl_sync(FULL, bs, 31);
            if (c) dst[bs + excl] = rec;
        }
        __syncthreads();
        mcur = s_cnt2;
        { unsigned long long* t = src; src = dst; dst = t; }
        if (mcur == 0) break;
        __syncthreads();
    }
    __syncthreads();
    if (tid == 0) g_mcnt[img] = s_mcnt;
}

// ---------------- k7: 8x4-bit LSD radix sort by death fbits -----------------
__global__ void __launch_bounds__(NTHR, 1) k_sort() {
    extern __shared__ char sm[];
    __shared__ uint32_t warpsum[32];
    uint32_t* hist = (uint32_t*)sm;                 // 64 KB
    const int img  = blockIdx.x;
    const int tid  = threadIdx.x;
    const int lane = tid & 31;
    const int wid  = tid >> 5;
    const unsigned FULL = 0xFFFFFFFFu;
    const int m2 = g_mcnt[img];
    const size_t off = (size_t)img * CAP;

    for (int pass = 0; pass < 8; pass++) {
        const unsigned long long* src = (pass & 1) ? g_mstB + off : g_mstA + off;
        unsigned long long*       dst = (pass & 1) ? g_mstA + off : g_mstB + off;
        const int shift = 32 + pass * 4;

        #pragma unroll
        for (int i = 0; i < 16; i++) hist[i * 1024 + tid] = 0;
        __syncthreads();

        const int bse = tid * 16;
        for (int j = 0; j < 16; j++) {
            int idx = bse + j;
            if (idx < m2) {
                uint32_t d = (uint32_t)(src[idx] >> shift) & 15u;
                hist[(d << 10) + tid]++;
            }
        }
        __syncthreads();

        const int sb = tid * 16;
        uint32_t sum = 0;
        #pragma unroll
        for (int i = 0; i < 16; i++) sum += hist[sb + i];
        uint32_t v = sum;
        #pragma unroll
        for (int o = 1; o < 32; o <<= 1) {
            uint32_t t = __shfl_up_sync(FULL, v, o);
            if (lane >= o) v += t;
        }
        if (lane == 31) warpsum[wid] = v;
        __syncthreads();
        if (wid == 0) {
            uint32_t w = warpsum[lane], wv = w;
            #pragma unroll
            for (int o = 1; o < 32; o <<= 1) {
                uint32_t t = __shfl_up_sync(FULL, wv, o);
                if (lane >= o) wv += t;
            }
            warpsum[lane] = wv - w;
        }
        __syncthreads();
        uint32_t run = (v - sum) + warpsum[wid];
        #pragma unroll
        for (int i = 0; i < 16; i++) { uint32_t t = hist[sb + i]; hist[sb + i] = run; run += t; }
        __syncthreads();

        for (int j = 0; j < 16; j++) {
            int idx = bse + j;
            if (idx < m2) {
                unsigned long long k = src[idx];
                uint32_t d = (uint32_t)(k >> shift) & 15u;
                dst[hist[(d << 10) + tid]++] = k;
            }
        }
        __syncthreads();
    }
}

// ---------------- k8: warp-parallel Kruskal pairing + loss + final ----------
__global__ void __launch_bounds__(NTHR, 1) k_pair(float* __restrict__ out) {
    extern __shared__ char sm[];
    __shared__ float cand2[32 * 5];
    const int img = blockIdx.x, tid = threadIdx.x;
    const int lane = tid & 31, wid = tid >> 5;
    const unsigned FULL = 0xFFFFFFFFu;
    uint16_t* par = (uint16_t*)sm;                     // 32 KB
    uint32_t* birth = (uint32_t*)(sm + 32768);         // 64 KB
    float*    life  = (float*)(sm + 98304);            // 64 KB
    const unsigned long long* __restrict__ mste = g_mstA + (size_t)img * CAP;
    const int nmin = g_nmin[img];
    const int m2 = g_mcnt[img];
    for (int i = tid; i < nmin; i += NTHR) {
        par[i] = (uint16_t)i;
        birth[i] = g_birth[(size_t)img * CAP + i];
    }
    __syncthreads();

    if (tid < 32) {
        for (int bs0 = 0; bs0 < m2; bs0 += 32) {       // uniform trip count
            int j = bs0 + lane;
            bool have = j < m2;
            unsigned long long e = have ? mste[j] : 0ull;
            uint32_t cu = (uint32_t)(e >> 16) & 0xFFFFu;
            uint32_t cv = (uint32_t)e & 0xFFFFu;
            float death = __uint_as_float((uint32_t)(e >> 32));
            bool done = !have;

            for (;;) {
                unsigned pend = __ballot_sync(FULL, !done);
                if (!pend) break;

                uint32_t ru, rv, die = 0xFFFFFFFFu, keep = 0;
                if (!done) {
                    ru = uf_find(par, cu);
                    rv = uf_find(par, cv);
                    uint32_t bu = birth[ru], bv = birth[rv];
                    bool ku = (bu < bv) || (bu == bv && ru < rv);  // elder survives
                    keep = ku ? ru : rv;
                    die  = ku ? rv : ru;
                } else {
                    ru = 0x20000u + lane * 2;
                    rv = ru + 1;
                }
                __syncwarp();

                // Phase A: die-hit blocking (independent, pipelined)
                bool blk = false;
                #pragma unroll
                for (int l = 0; l < 31; l++) {
                    uint32_t dl = __shfl_sync(FULL, die, l);
                    if (lane > l && !done && (dl == ru || dl == rv)) blk = true;
                }

                // Phase B: propagate (blocked & share) to ballot fixpoint
                unsigned bm = __ballot_sync(FULL, !done && blk);
                for (;;) {
                    bool nblk = blk;
                    #pragma unroll
                    for (int l = 0; l < 31; l++) {
                        uint32_t rul = __shfl_sync(FULL, ru, l);
                        uint32_t rvl = __shfl_sync(FULL, rv, l);
                        if (lane > l && !done && ((bm >> l) & 1u) &&
                            (rul == ru || rul == rv || rvl == ru || rvl == rv))
                            nblk = true;
                    }
                    unsigned nbm = __ballot_sync(FULL, !done && nblk);
                    blk = nblk;
                    if (nbm == bm) break;
                    bm = nbm;
                }

                if (!done && !blk) {
                    par[die] = (uint16_t)keep;
                    life[j] = death - __uint_as_float(birth[die]);
                    done = true;
                }
                __syncwarp();
            }
        }
    }
    __syncthreads();

    // top-5: per-thread regs -> warp shuffle merge -> tiny final scan
    float t0 = -1e30f, t1 = -1e30f, t2 = -1e30f, t3 = -1e30f, t4 = -1e30f;
    for (int i = tid; i < m2; i += NTHR) top5_ins(t0, t1, t2, t3, t4, life[i]);
    #pragma unroll
    for (int o = 16; o > 0; o >>= 1) {
        float a0 = __shfl_down_sync(FULL, t0, o);
        float a1 = __shfl_down_sync(FULL, t1, o);
        float a2 = __shfl_down_sync(FULL, t2, o);
        float a3 = __shfl_down_sync(FULL, t3, o);
        float a4 = __shfl_down_sync(FULL, t4, o);
        top5_ins(t0, t1, t2, t3, t4, a0);
        top5_ins(t0, t1, t2, t3, t4, a1);
        top5_ins(t0, t1, t2, t3, t4, a2);
        top5_ins(t0, t1, t2, t3, t4, a3);
        top5_ins(t0, t1, t2, t3, t4, a4);
    }
    if (lane == 0) {
        cand2[wid * 5 + 0] = t0; cand2[wid * 5 + 1] = t1; cand2[wid * 5 + 2] = t2;
        cand2[wid * 5 + 3] = t3; cand2[wid * 5 + 4] = t4;
    }
    __syncthreads();
    if (tid == 0) {
        float s0 = -1e30f, s1 = -1e30f, s2 = -1e30f, s3 = -1e30f, s4 = -1e30f;
        for (int i = 0; i < 32 * 5; i++) top5_ins(s0, s1, s2, s3, s4, cand2[i]);
        if (s0 < -1e29f) s0 = 0.0f;            // pad with 0-life pairs
        if (s1 < -1e29f) s1 = 0.0f;
        if (s2 < -1e29f) s2 = 0.0f;
        if (s3 < -1e29f) s3 = 0.0f;
        if (s4 < -1e29f) s4 = 0.0f;
        float d0 = s0 - 0.5f, d1 = s1 - 0.5f, d2 = s2 - 0.5f, d3 = s3 - 0.5f, d4 = s4 - 0.5f;
        g_loss[img] = (d0 * d0 + d1 * d1 + d2 * d2 + d3 * d3 + d4 * d4) * 0.2f;

        __threadfence();
        int old = atomicAdd(&g_done, 1);
        if (old == NIMG - 1) {
            __threadfence();
            out[0] = (g_loss[0] + g_loss[1] + g_loss[2] + g_loss[3]) * 25.0f;
            g_done = 0;                        // reset for next graph replay
        }
    }
}

// ---------------- launch -----------------------------------------------------
extern "C" void kernel_launch(void* const* d_in, const int* in_sizes, int n_in,
                              void* d_out, int out_size) {
    (void)in_sizes; (void)n_in; (void)out_size;
    const float* prob = (const float*)d_in[0];
    const float* roi  = (const float*)d_in[1];
    float* out = (float*)d_out;

    cudaFuncSetAttribute(k_boruvka, cudaFuncAttributeMaxDynamicSharedMemorySize, 160 * 1024);
    cudaFuncSetAttribute(k_sort,    cudaFuncAttributeMaxDynamicSharedMemorySize, 64 * 1024);
    cudaFuncSetAttribute(k_pair,    cudaFuncAttributeMaxDynamicSharedMemorySize, 160 * 1024);

    k_init<<<NBLK, NTHR>>>(prob, roi);
    k_desc<<<NBLK, NTHR>>>();
    k_walk<<<NBLK, NTHR>>>();
    k_dense<<<NIMG, NTHR>>>();
    k_edges<<<NBLK, NTHR>>>();
    k_boruvka<<<NIMG, NTHR, 160 * 1024>>>();
    k_sort<<<NIMG, NTHR, 64 * 1024>>>();
    k_pair<<<NIMG, NTHR, 160 * 1024>>>(out);
}